// round 15
// baseline (speedup 1.0000x reference)
#include <cuda_runtime.h>
#include <math.h>

// ---------- tf32 MMA (raw fp32 bits; HW truncates to tf32) ----------
__device__ __forceinline__ void mma_tf32(float* d, const unsigned* a, const unsigned* b) {
    asm("mma.sync.aligned.m16n8k8.row.col.f32.tf32.tf32.f32 "
        "{%0,%1,%2,%3}, {%4,%5,%6,%7}, {%8,%9}, {%0,%1,%2,%3};"
        : "+f"(d[0]), "+f"(d[1]), "+f"(d[2]), "+f"(d[3])
        : "r"(a[0]), "r"(a[1]), "r"(a[2]), "r"(a[3]), "r"(b[0]), "r"(b[1]));
}
__device__ __forceinline__ void cpa16(void* dst, const void* src) {
    unsigned s = (unsigned)__cvta_generic_to_shared(dst);
    asm volatile("cp.async.cg.shared.global [%0], [%1], 16;" :: "r"(s), "l"(src));
}
#define CP_COMMIT asm volatile("cp.async.commit_group;")
#define CP_WAIT1  asm volatile("cp.async.wait_group 1;")
#define CP_WAIT0  asm volatile("cp.async.wait_group 0;")

#define S1R 780   // s1 row stride; data at [7, 7+751)
#define S2R 396   // s2 row stride; data at [8, 8+377)

// ---------- scratch ----------
__device__ float g_s1[768*64*S1R];
__device__ float g_s2[768*128*S2R];
__device__ float g_s3[768*128*191];
__device__ float g_wt2[64*3*128];
__device__ float g_wt3[128*3*128];
__device__ float g_mp[16*768*256];
__device__ float g_a [768*256];
__device__ float g_feats[32*4096];

// ---------- weight transpose: w[oc][ic][tap] -> wT[ch][tap*16+icl][oc] ----------
__global__ void k_wt(const float* __restrict__ w, float* __restrict__ wT, int IC) {
    int idx = blockIdx.x*256 + threadIdx.x;
    if (idx >= 128*IC*3) return;
    int oc = idx / (IC*3), r = idx - oc*(IC*3);
    int ic = r / 3, tap = r - ic*3;
    int ch = ic >> 4, icl = ic & 15;
    wT[ch*6144 + (tap*16+icl)*128 + oc] = w[idx];
}

// ---------- conv1 (1->64,K=3,pad=1)+BN+ReLU+maxpool2(pad=1): coalesced, 1 pooled/thread ----------
__global__ __launch_bounds__(256)
void k_conv1(const float* __restrict__ x, const float* __restrict__ w,
             const float* __restrict__ bn, float* __restrict__ out) {
    __shared__ float xs[516];
    __shared__ float ws[192];
    __shared__ float sc[64], sh[64];
    const int b = blockIdx.x, j0 = blockIdx.y * 256, tid = threadIdx.x;
    if (tid < 192) ws[tid] = w[tid];
    if (tid >= 192 && tid < 256) {
        int o = tid - 192;
        float s = bn[o] * rsqrtf(bn[192+o] + 1e-5f);
        sc[o] = s; sh[o] = bn[64+o] - bn[128+o]*s;
    }
    const int base = 2*j0 - 2;
    for (int i = tid; i < 514; i += 256) {
        int gi = base + i;
        xs[i] = (gi >= 0 && gi < 1500) ? x[b*1500 + gi] : 0.f;
    }
    __syncthreads();
    if (blockIdx.y == 0) {
        for (int i = tid; i < 64*7; i += 256)
            out[(size_t)(b*64 + i/7)*S1R + (i%7)] = 0.f;
    } else if (blockIdx.y == 2) {
        for (int i = tid; i < 64*22; i += 256)
            out[(size_t)(b*64 + i/22)*S1R + 758 + (i%22)] = 0.f;
    }
    const int j = j0 + tid;
    if (j > 750) return;
    const float a0 = xs[2*tid], a1 = xs[2*tid+1], a2 = xs[2*tid+2], a3 = xs[2*tid+3];
    const bool vL = (j > 0), vR = (j < 750);
    float* ob = out + (size_t)b*64*S1R + 7 + j;
    #pragma unroll 4
    for (int oc = 0; oc < 64; oc++) {
        float w0 = ws[3*oc], w1 = ws[3*oc+1], w2 = ws[3*oc+2];
        float s = sc[oc], h = sh[oc];
        float r0 = fmaf(w2, a2, fmaf(w1, a1, w0*a0));
        float r1 = fmaf(w2, a3, fmaf(w1, a2, w0*a1));
        r0 = fmaxf(fmaf(r0, s, h), 0.f);
        r1 = fmaxf(fmaf(r1, s, h), 0.f);
        ob[(size_t)oc*S1R] = fmaxf(vL ? r0 : -1e30f, vR ? r1 : -1e30f);
    }
}

// ---------- conv (IC->128,K=3)+BN+ReLU+pool via tf32 MMA, software-pipelined fragments ----------
// 128 thr = 4 warps (2wm x 2wn); warp tile 64oc x 64 conv pos; block 128 x 128 (64 pooled).
template<int IC, int PAD, int XSTR, int XOFF, int JOUT, int OSTR, int OOFF>
__global__ __launch_bounds__(128, 2)
void k_conv_mma(const float* __restrict__ x, const float* __restrict__ wT,
                const float* __restrict__ bn, float* __restrict__ out) {
    __shared__ unsigned Wt[2][48*136];
    __shared__ unsigned Xt[2][16][136];
    __shared__ float sc[128], sh[128];
    const int b = blockIdx.x, p0 = blockIdx.y * 64;
    const int tid = threadIdx.x, lane = tid & 31, warp = tid >> 5;
    const int wm = warp & 1, wn = warp >> 1;
    const int grp = lane >> 2, tq = lane & 3;
    {
        float s = bn[tid] * rsqrtf(bn[384+tid] + 1e-5f);
        sc[tid] = s; sh[tid] = bn[128+tid] - bn[256+tid]*s;
    }
    float c[4][8][4];
    #pragma unroll
    for (int mt = 0; mt < 4; mt++)
        #pragma unroll
        for (int nt = 0; nt < 8; nt++)
            #pragma unroll
            for (int q = 0; q < 4; q++) c[mt][nt][q] = 0.f;
    const int xbase = XOFF + 2*p0 - 1 - PAD;
    const float* xb = x + (size_t)b*IC*XSTR;
    const int NCH = IC/16;

    auto stage = [&](int ch, int buf) {
        for (int i = tid; i < 1536; i += 128) {
            int row = i >> 5, col4 = i & 31;
            cpa16(&Wt[buf][row*136 + col4*4], wT + (size_t)ch*6144 + row*128 + col4*4);
        }
        for (int i = tid; i < 16*34; i += 128) {
            int r = i / 34, c4 = i - r*34;
            cpa16(&Xt[buf][r][c4*4], xb + (size_t)(ch*16+r)*XSTR + xbase + c4*4);
        }
        CP_COMMIT;
    };

    stage(0, 0);
    for (int ch = 0; ch < NCH; ch++) {
        bool more = (ch + 1 < NCH);
        if (more) stage(ch+1, (ch+1)&1);
        if (more) { CP_WAIT1; } else { CP_WAIT0; }
        __syncthreads();
        const int bq = ch & 1;
        // software-pipelined fragments: step = ks*3 + t, double-buffered
        unsigned a[2][4][4], bf[2][8][2];
        auto ldfrag = [&](int step, int sel) {
            const int ks = step / 3, t = step - ks*3;
            const int kr = ks*8 + tq;
            #pragma unroll
            for (int mt = 0; mt < 4; mt++) {
                int om = wm*64 + mt*16 + grp;
                a[sel][mt][0] = Wt[bq][(t*16+kr  )*136 + om];
                a[sel][mt][1] = Wt[bq][(t*16+kr  )*136 + om+8];
                a[sel][mt][2] = Wt[bq][(t*16+kr+4)*136 + om];
                a[sel][mt][3] = Wt[bq][(t*16+kr+4)*136 + om+8];
            }
            #pragma unroll
            for (int nt = 0; nt < 8; nt++) {
                int cc = wn*64 + nt*8 + grp + t;
                bf[sel][nt][0] = Xt[bq][kr  ][cc];
                bf[sel][nt][1] = Xt[bq][kr+4][cc];
            }
        };
        ldfrag(0, 0);
        #pragma unroll
        for (int step = 0; step < 6; step++) {
            if (step < 5) ldfrag(step+1, (step+1)&1);
            const int sel = step & 1;
            #pragma unroll
            for (int mt = 0; mt < 4; mt++)
                #pragma unroll
                for (int nt = 0; nt < 8; nt++)
                    mma_tf32(c[mt][nt], a[sel][mt], bf[sel][nt]);
        }
        __syncthreads();
    }
    if (OOFF > 0) {
        if (blockIdx.y == 0) {
            for (int i = tid; i < 128*OOFF; i += 128)
                out[(size_t)(b*128 + i/OOFF)*OSTR + (i%OOFF)] = 0.f;
        }
        if (p0 + 64 >= JOUT) {
            const int TW = OSTR - OOFF - JOUT;
            for (int i = tid; i < 128*TW; i += 128)
                out[(size_t)(b*128 + i/TW)*OSTR + OOFF + JOUT + (i%TW)] = 0.f;
        }
    }
    #pragma unroll
    for (int mt = 0; mt < 4; mt++) {
        int ocr = wm*64 + mt*16 + grp;
        #pragma unroll
        for (int nt = 0; nt < 8; nt++) {
            int lp = wn*64 + nt*8 + tq*2;
            int j = p0 + (lp >> 1);
            if (j < JOUT) {
                #pragma unroll
                for (int rr = 0; rr < 2; rr++) {
                    int oc = ocr + rr*8;
                    float s = sc[oc], h = sh[oc];
                    float r0 = fmaxf(fmaf(c[mt][nt][rr*2],   s, h), 0.f);
                    float r1 = fmaxf(fmaf(c[mt][nt][rr*2+1], s, h), 0.f);
                    out[(size_t)(b*128+oc)*OSTR + OOFF + j] = (j == 0) ? r1 : fmaxf(r0, r1);
                }
            }
        }
    }
}

// ---------- map2 GEMM [768,24448]x[24448,256], tf32 MMA, split-K=16 ----------
__global__ __launch_bounds__(128)
void k_map2_mma(const float* __restrict__ A, const float* __restrict__ Bw, float* __restrict__ P) {
    __shared__ unsigned At[2][64][36];
    __shared__ unsigned Bt[2][32][72];
    const int m0 = blockIdx.x*64, n0 = blockIdx.y*64;
    const int k0 = blockIdx.z*1536;
    const int kend = (k0 + 1536 < 24448) ? k0 + 1536 : 24448;
    const int niter = (kend - k0) >> 5;
    const int tid = threadIdx.x, lane = tid & 31, warp = tid >> 5;
    const int wm = warp & 1, wn = warp >> 1;
    const int grp = lane >> 2, tq = lane & 3;
    float c[2][4][4];
    #pragma unroll
    for (int mt = 0; mt < 2; mt++)
        #pragma unroll
        for (int nt = 0; nt < 4; nt++)
            #pragma unroll
            for (int q = 0; q < 4; q++) c[mt][nt][q] = 0.f;

    auto stage = [&](int it, int buf) {
        int kc = k0 + it*32;
        #pragma unroll
        for (int s = 0; s < 4; s++) {
            int idx = tid + 128*s;
            int row = idx >> 3, c4 = idx & 7;
            cpa16(&At[buf][row][c4*4], &A[(size_t)(m0+row)*24448 + kc + c4*4]);
        }
        #pragma unroll
        for (int s = 0; s < 4; s++) {
            int idx = tid + 128*s;
            int row = idx >> 4, c4 = idx & 15;
            cpa16(&Bt[buf][row][c4*4], &Bw[(size_t)(kc+row)*256 + n0 + c4*4]);
        }
        CP_COMMIT;
    };

    stage(0, 0);
    for (int it = 0; it < niter; it++) {
        bool more = (it + 1 < niter);
        if (more) stage(it+1, (it+1)&1);
        if (more) { CP_WAIT1; } else { CP_WAIT0; }
        __syncthreads();
        const int bq = it & 1;
        #pragma unroll
        for (int ks = 0; ks < 4; ks++) {
            const int kr = ks*8 + tq;
            unsigned a[2][4], bf[4][2];
            #pragma unroll
            for (int mt = 0; mt < 2; mt++) {
                int om = wm*32 + mt*16 + grp;
                a[mt][0] = At[bq][om  ][kr];   a[mt][1] = At[bq][om+8][kr];
                a[mt][2] = At[bq][om  ][kr+4]; a[mt][3] = At[bq][om+8][kr+4];
            }
            #pragma unroll
            for (int nt = 0; nt < 4; nt++) {
                int cc = wn*32 + nt*8 + grp;
                bf[nt][0] = Bt[bq][kr  ][cc];
                bf[nt][1] = Bt[bq][kr+4][cc];
            }
            #pragma unroll
            for (int mt = 0; mt < 2; mt++)
                #pragma unroll
                for (int nt = 0; nt < 4; nt++)
                    mma_tf32(c[mt][nt], a[mt], bf[nt]);
        }
        __syncthreads();
    }
    #pragma unroll
    for (int mt = 0; mt < 2; mt++) {
        int row = m0 + wm*32 + mt*16 + grp;
        #pragma unroll
        for (int nt = 0; nt < 4; nt++) {
            int col = n0 + wn*32 + nt*8 + tq*2;
            *(float2*)&P[(size_t)(blockIdx.z*768 + row    )*256 + col] = make_float2(c[mt][nt][0], c[mt][nt][1]);
            *(float2*)&P[(size_t)(blockIdx.z*768 + row + 8)*256 + col] = make_float2(c[mt][nt][2], c[mt][nt][3]);
        }
    }
}

// ---------- split-K combine + bias + BN + positional encoding ----------
__global__ void k_combine(const float* __restrict__ mp, const float* __restrict__ mb,
                          const float* __restrict__ bnm, float* __restrict__ a) {
    const int row = blockIdx.x, f = threadIdx.x;
    float s = 0.f;
    #pragma unroll
    for (int z = 0; z < 16; z++) s += mp[(z*768+row)*256+f];
    s += mb[f];
    s = fmaf(s - bnm[512+f], bnm[f] * rsqrtf(bnm[768+f] + 1e-5f), bnm[256+f]);
    const int t = (row >> 2) % 6;
    const float div = expf((float)((f >> 1) * 2) * (-4.605170185988091f / 256.f));
    const float ang = (float)t * div;
    a[row*256+f] = s + ((f & 1) ? cosf(ang) : sinf(ang));
}

// ---------- fused branch: graphf + adjacency + MPNN for both windows ----------
__global__ __launch_bounds__(256)
void k_branch(const float* __restrict__ a,
              const float* __restrict__ g1_w, const float* __restrict__ g1_b,
              const float* __restrict__ bnA1, const float* __restrict__ th1_w,
              const float* __restrict__ th1_b, const float* __restrict__ bnM1,
              const float* __restrict__ g2_w, const float* __restrict__ g2_b,
              const float* __restrict__ bnA2, const float* __restrict__ th2_w,
              const float* __restrict__ th2_b, const float* __restrict__ bnM2,
              float* __restrict__ feats) {
    const int g = blockIdx.x, tid = threadIdx.x;
    const bool w1 = g < 160;
    const float* gw  = w1 ? g1_w : g2_w;
    const float* gb  = w1 ? g1_b : g2_b;
    const float* bnA = w1 ? bnA1 : bnA2;
    const float* tw  = w1 ? th1_w : th2_w;
    const float* tb  = w1 ? th1_b : th2_b;
    const float* bnM = w1 ? bnM1 : bnM2;
    const int gg = w1 ? g : g - 160;
    const int nw = w1 ? 5 : 3, stride = w1 ? 1 : 2, off = w1 ? 0 : 2560;
    const int bs = gg / nw, j = gg % nw;

    __shared__ float Xc[8][257];
    __shared__ float fs[8][257];
    __shared__ float dots[64];
    __shared__ float Aj[64];
    __shared__ float part[2][8][128];

    #pragma unroll
    for (int n = 0; n < 8; n++) {
        int row = (bs*6 + j*stride + (n>>2))*4 + (n&3);
        Xc[n][tid] = a[row*256 + tid];
    }
    __syncthreads();
    {
        float acc[8], bias = gb[tid];
        #pragma unroll
        for (int n = 0; n < 8; n++) acc[n] = bias;
        #pragma unroll 4
        for (int d = 0; d < 256; d++) {
            float wv = gw[d*256 + tid];
            #pragma unroll
            for (int n = 0; n < 8; n++) acc[n] = fmaf(Xc[n][d], wv, acc[n]);
        }
        #pragma unroll
        for (int n = 0; n < 8; n++) fs[n][tid] = acc[n];
    }
    __syncthreads();
    {
        int pr = tid >> 2, tq = tid & 3, n = pr >> 3, m = pr & 7;
        float dp = 0.f;
        #pragma unroll 4
        for (int i = 0; i < 64; i++) {
            int d = tq*64 + i;
            dp = fmaf(fs[n][d], fs[m][d], dp);
        }
        dp += __shfl_xor_sync(0xffffffffu, dp, 1, 4);
        dp += __shfl_xor_sync(0xffffffffu, dp, 2, 4);
        if (tq == 0) dots[pr] = dp;
    }
    __syncthreads();
    if (tid < 64) {
        int n = tid >> 3, m = tid & 7;
        float dot = dots[tid];
        if (n == m) dot -= 1e8f;
        float v = dot > 0.f ? dot : 0.01f*dot;
        float mx = v;
        #pragma unroll
        for (int o = 1; o < 8; o <<= 1) mx = fmaxf(mx, __shfl_xor_sync(0xffffffffu, mx, o, 8));
        float e = expf(v - mx), ssum = e;
        #pragma unroll
        for (int o = 1; o < 8; o <<= 1) ssum += __shfl_xor_sync(0xffffffffu, ssum, o, 8);
        float av = e / ssum;
        if (n == m) av += 1.f;
        Aj[tid] = av * (((n>>2) == (m>>2)) ? 1.f : 0.7f);
    }
    {
        float s = bnA[tid] * rsqrtf(bnA[768+tid] + 1e-5f);
        float sh = bnA[256+tid] - bnA[512+tid]*s;
        #pragma unroll
        for (int n = 0; n < 8; n++) Xc[n][tid] = fmaf(Xc[n][tid], s, sh);
    }
    __syncthreads();
    #pragma unroll
    for (int n = 0; n < 8; n++) {
        float ys = 0.f;
        #pragma unroll
        for (int m = 0; m < 8; m++) ys = fmaf(Aj[n*8+m], Xc[m][tid], ys);
        fs[n][tid] = ys;
    }
    __syncthreads();
    {
        int half = tid >> 7, o = tid & 127;
        float hac[8];
        #pragma unroll
        for (int n = 0; n < 8; n++) hac[n] = 0.f;
        #pragma unroll 4
        for (int dd = 0; dd < 128; dd++) {
            int d = half*128 + dd;
            float wv = tw[d*128 + o];
            #pragma unroll
            for (int n = 0; n < 8; n++) hac[n] = fmaf(fs[n][d], wv, hac[n]);
        }
        #pragma unroll
        for (int n = 0; n < 8; n++) part[half][n][o] = hac[n];
    }
    __syncthreads();
    if (tid < 128) {
        int o = tid;
        float s = bnM[o] * rsqrtf(bnM[384+o] + 1e-5f);
        float sh = bnM[128+o] - bnM[256+o]*s;
        float hv[8];
        #pragma unroll
        for (int n = 0; n < 8; n++) {
            float z = part[0][n][o] + part[1][n][o] + tb[o];
            z = fmaf(z, s, sh);
            hv[n] = z > 0.f ? z : 0.01f*z;
        }
        #pragma unroll
        for (int ns = 0; ns < 4; ns++)
            feats[bs*4096 + off + (j*4+ns)*128 + o] = 0.5f*(hv[ns] + hv[4+ns]);
    }
}

// ---------- fc1 split-K partials ----------
__global__ __launch_bounds__(256)
void k_fc1p(const float* __restrict__ x, const float* __restrict__ w, float* __restrict__ P) {
    __shared__ float xs[1024];
    const int row = blockIdx.x, ks = blockIdx.y, tid = threadIdx.x;
    for (int i = tid; i < 1024; i += 256) xs[i] = x[row*4096 + ks*1024 + i];
    __syncthreads();
    float a0 = 0.f, a1 = 0.f, a2 = 0.f, a3 = 0.f;
    const float* wp = w + (size_t)ks*1024*256 + tid;
    for (int k = 0; k < 1024; k += 4) {
        a0 = fmaf(xs[k],   wp[(size_t)k*256],       a0);
        a1 = fmaf(xs[k+1], wp[(size_t)(k+1)*256],   a1);
        a2 = fmaf(xs[k+2], wp[(size_t)(k+2)*256],   a2);
        a3 = fmaf(xs[k+3], wp[(size_t)(k+3)*256],   a3);
    }
    P[(ks*32 + row)*256 + tid] = (a0 + a1) + (a2 + a3);
}

// ---------- fc1-combine + relu + fc2 + fc3 + fc4 fused ----------
__global__ __launch_bounds__(256)
void k_fchain(const float* __restrict__ P, const float* __restrict__ b1,
              const float* __restrict__ w2, const float* __restrict__ b2,
              const float* __restrict__ w3, const float* __restrict__ b3,
              const float* __restrict__ w4, const float* __restrict__ b4,
              float* __restrict__ out) {
    __shared__ float xs[256], ys[256], zs[128];
    const int row = blockIdx.x, tid = threadIdx.x;
    {
        float v = P[row*256+tid] + P[(32+row)*256+tid] + P[(64+row)*256+tid] + P[(96+row)*256+tid];
        xs[tid] = fmaxf(v + b1[tid], 0.f);
    }
    __syncthreads();
    {
        float acc = b2[tid];
        #pragma unroll 4
        for (int k = 0; k < 256; k++) acc = fmaf(xs[k], w2[k*256+tid], acc);
        ys[tid] = fmaxf(acc, 0.f);
    }
    __syncthreads();
    if (tid < 128) {
        float acc = b3[tid];
        #pragma unroll 4
        for (int k = 0; k < 256; k++) acc = fmaf(ys[k], w3[k*128+tid], acc);
        zs[tid] = fmaxf(acc, 0.f);
    }
    __syncthreads();
    if (tid < 5) {
        float acc = b4[tid];
        for (int k = 0; k < 128; k++) acc = fmaf(zs[k], w4[k*5+tid], acc);
        out[row*5+tid] = acc;
    }
}

extern "C" void kernel_launch(void* const* d_in, const int* in_sizes, int n_in,
                              void* d_out, int out_size) {
    const float* X       = (const float*)d_in[0];
    const float* conv1_w = (const float*)d_in[1];
    const float* bn1     = (const float*)d_in[2];
    const float* conv2_w = (const float*)d_in[3];
    const float* bn2     = (const float*)d_in[4];
    const float* conv3_w = (const float*)d_in[5];
    const float* bn3     = (const float*)d_in[6];
    const float* map2_w  = (const float*)d_in[7];
    const float* map2_b  = (const float*)d_in[8];
    const float* bn_map2 = (const float*)d_in[9];
    const float* g1_w = (const float*)d_in[10], *g1_b = (const float*)d_in[11], *bnA1 = (const float*)d_in[12];
    const float* th1_w = (const float*)d_in[13], *th1_b = (const float*)d_in[14], *bnM1 = (const float*)d_in[15];
    const float* g2_w = (const float*)d_in[16], *g2_b = (const float*)d_in[17], *bnA2 = (const float*)d_in[18];
    const float* th2_w = (const float*)d_in[19], *th2_b = (const float*)d_in[20], *bnM2 = (const float*)d_in[21];
    const float* fc1_w = (const float*)d_in[22], *fc1_b = (const float*)d_in[23];
    const float* fc2_w = (const float*)d_in[24], *fc2_b = (const float*)d_in[25];
    const float* fc3_w = (const float*)d_in[26], *fc3_b = (const float*)d_in[27];
    const float* fc4_w = (const float*)d_in[28], *fc4_b = (const float*)d_in[29];

    void* p;
    cudaGetSymbolAddress(&p, g_s1);   float* s1 = (float*)p;
    cudaGetSymbolAddress(&p, g_s2);   float* s2 = (float*)p;
    cudaGetSymbolAddress(&p, g_s3);   float* s3 = (float*)p;
    cudaGetSymbolAddress(&p, g_wt2);  float* wt2 = (float*)p;
    cudaGetSymbolAddress(&p, g_wt3);  float* wt3 = (float*)p;
    cudaGetSymbolAddress(&p, g_mp);   float* mp = (float*)p;
    cudaGetSymbolAddress(&p, g_a);    float* a  = (float*)p;
    cudaGetSymbolAddress(&p, g_feats);float* feats = (float*)p;

    k_wt<<<(128*64*3+255)/256, 256>>>(conv2_w, wt2, 64);
    k_wt<<<(128*128*3+255)/256, 256>>>(conv3_w, wt3, 128);
    k_conv1<<<dim3(768,3), 256>>>(X, conv1_w, bn1, s1);
    k_conv_mma<64,2,S1R,7,377,S2R,8><<<dim3(768,6), 128>>>(s1, wt2, bn2, s2);
    k_conv_mma<128,3,S2R,8,191,191,0><<<dim3(768,3), 128>>>(s2, wt3, bn3, s3);
    k_map2_mma<<<dim3(12,4,16), 128>>>(s3, map2_w, mp);
    k_combine<<<768, 256>>>(mp, map2_b, bn_map2, a);
    k_branch<<<256, 256>>>(a, g1_w, g1_b, bnA1, th1_w, th1_b, bnM1,
                              g2_w, g2_b, bnA2, th2_w, th2_b, bnM2, feats);
    k_fc1p<<<dim3(32,4), 256>>>(feats, fc1_w, mp);
    k_fchain<<<32, 256>>>(mp, fc1_b, fc2_w, fc2_b, fc3_w, fc3_b, fc4_w, fc4_b, (float*)d_out);
}

// round 16
// speedup vs baseline: 1.0007x; 1.0007x over previous
#include <cuda_runtime.h>
#include <math.h>

// ---------- tf32 MMA (raw fp32 bits; HW truncates to tf32) ----------
__device__ __forceinline__ void mma_tf32(float* d, const unsigned* a, const unsigned* b) {
    asm("mma.sync.aligned.m16n8k8.row.col.f32.tf32.tf32.f32 "
        "{%0,%1,%2,%3}, {%4,%5,%6,%7}, {%8,%9}, {%0,%1,%2,%3};"
        : "+f"(d[0]), "+f"(d[1]), "+f"(d[2]), "+f"(d[3])
        : "r"(a[0]), "r"(a[1]), "r"(a[2]), "r"(a[3]), "r"(b[0]), "r"(b[1]));
}
__device__ __forceinline__ void cpa16(void* dst, const void* src) {
    unsigned s = (unsigned)__cvta_generic_to_shared(dst);
    asm volatile("cp.async.cg.shared.global [%0], [%1], 16;" :: "r"(s), "l"(src));
}
#define CP_COMMIT asm volatile("cp.async.commit_group;")
#define CP_WAIT1  asm volatile("cp.async.wait_group 1;")
#define CP_WAIT0  asm volatile("cp.async.wait_group 0;")

#define S1R 780   // s1 row stride; data at [7, 7+751)
#define S2R 396   // s2 row stride; data at [8, 8+377)

// ---------- scratch ----------
__device__ float g_s1[768*64*S1R];
__device__ float g_s2[768*128*S2R];
__device__ float g_s3[768*128*191];
__device__ float g_wt2[64*3*128];
__device__ float g_wt3[128*3*128];
__device__ float g_mp[16*768*256];
__device__ float g_a [768*256];
__device__ float g_feats[32*4096];

// ---------- weight transpose: w[oc][ic][tap] -> wT[ch][tap*16+icl][oc] ----------
__global__ void k_wt(const float* __restrict__ w, float* __restrict__ wT, int IC) {
    int idx = blockIdx.x*256 + threadIdx.x;
    if (idx >= 128*IC*3) return;
    int oc = idx / (IC*3), r = idx - oc*(IC*3);
    int ic = r / 3, tap = r - ic*3;
    int ch = ic >> 4, icl = ic & 15;
    wT[ch*6144 + (tap*16+icl)*128 + oc] = w[idx];
}

// ---------- conv1 (1->64,K=3,pad=1)+BN+ReLU+maxpool2(pad=1): coalesced, 1 pooled/thread ----------
__global__ __launch_bounds__(256)
void k_conv1(const float* __restrict__ x, const float* __restrict__ w,
             const float* __restrict__ bn, float* __restrict__ out) {
    __shared__ float xs[516];
    __shared__ float ws[192];
    __shared__ float sc[64], sh[64];
    const int b = blockIdx.x, j0 = blockIdx.y * 256, tid = threadIdx.x;
    if (tid < 192) ws[tid] = w[tid];
    if (tid >= 192 && tid < 256) {
        int o = tid - 192;
        float s = bn[o] * rsqrtf(bn[192+o] + 1e-5f);
        sc[o] = s; sh[o] = bn[64+o] - bn[128+o]*s;
    }
    const int base = 2*j0 - 2;
    for (int i = tid; i < 514; i += 256) {
        int gi = base + i;
        xs[i] = (gi >= 0 && gi < 1500) ? x[b*1500 + gi] : 0.f;
    }
    __syncthreads();
    if (blockIdx.y == 0) {
        for (int i = tid; i < 64*7; i += 256)
            out[(size_t)(b*64 + i/7)*S1R + (i%7)] = 0.f;
    } else if (blockIdx.y == 2) {
        for (int i = tid; i < 64*22; i += 256)
            out[(size_t)(b*64 + i/22)*S1R + 758 + (i%22)] = 0.f;
    }
    const int j = j0 + tid;
    if (j > 750) return;
    const float a0 = xs[2*tid], a1 = xs[2*tid+1], a2 = xs[2*tid+2], a3 = xs[2*tid+3];
    const bool vL = (j > 0), vR = (j < 750);
    float* ob = out + (size_t)b*64*S1R + 7 + j;
    #pragma unroll 4
    for (int oc = 0; oc < 64; oc++) {
        float w0 = ws[3*oc], w1 = ws[3*oc+1], w2 = ws[3*oc+2];
        float s = sc[oc], h = sh[oc];
        float r0 = fmaf(w2, a2, fmaf(w1, a1, w0*a0));
        float r1 = fmaf(w2, a3, fmaf(w1, a2, w0*a1));
        r0 = fmaxf(fmaf(r0, s, h), 0.f);
        r1 = fmaxf(fmaf(r1, s, h), 0.f);
        ob[(size_t)oc*S1R] = fmaxf(vL ? r0 : -1e30f, vR ? r1 : -1e30f);
    }
}

// ---------- conv (IC->128,K=3)+BN+ReLU+pool via tf32 MMA ----------
// Block: 64 oc (z-half) x 128 conv pos (64 pooled); 4 warps (2wm x 2wn), warp tile 32x64.
// 3 blocks/SM (12 warps) so barriers/fill waits of one block hide under another's MMAs.
template<int IC, int PAD, int XSTR, int XOFF, int JOUT, int OSTR, int OOFF>
__global__ __launch_bounds__(128, 3)
void k_conv_mma(const float* __restrict__ x, const float* __restrict__ wT,
                const float* __restrict__ bn, float* __restrict__ out) {
    __shared__ unsigned Wt[2][48*72];     // [buf][tap*16+icl][oc_half 64 +8 pad]
    __shared__ unsigned Xt[2][16][136];
    __shared__ float sc[64], sh[64];
    const int b = blockIdx.x, p0 = blockIdx.y * 64, oh = blockIdx.z;   // oc half
    const int tid = threadIdx.x, lane = tid & 31, warp = tid >> 5;
    const int wm = warp & 1, wn = warp >> 1;
    const int grp = lane >> 2, tq = lane & 3;
    if (tid < 64) {
        int oc = oh*64 + tid;
        float s = bn[oc] * rsqrtf(bn[384+oc] + 1e-5f);
        sc[tid] = s; sh[tid] = bn[128+oc] - bn[256+oc]*s;
    }
    float c[2][8][4];
    #pragma unroll
    for (int mt = 0; mt < 2; mt++)
        #pragma unroll
        for (int nt = 0; nt < 8; nt++)
            #pragma unroll
            for (int q = 0; q < 4; q++) c[mt][nt][q] = 0.f;
    const int xbase = XOFF + 2*p0 - 1 - PAD;
    const float* xb = x + (size_t)b*IC*XSTR;
    const int NCH = IC/16;

    auto stage = [&](int ch, int buf) {
        for (int i = tid; i < 768; i += 128) {          // W: 48 rows x 16 float4 (64 oc)
            int row = i >> 4, col4 = i & 15;
            cpa16(&Wt[buf][row*72 + col4*4], wT + (size_t)ch*6144 + row*128 + oh*64 + col4*4);
        }
        for (int i = tid; i < 16*34; i += 128) {        // X: 16 rows x 34 float4
            int r = i / 34, c4 = i - r*34;
            cpa16(&Xt[buf][r][c4*4], xb + (size_t)(ch*16+r)*XSTR + xbase + c4*4);
        }
        CP_COMMIT;
    };

    stage(0, 0);
    for (int ch = 0; ch < NCH; ch++) {
        bool more = (ch + 1 < NCH);
        if (more) stage(ch+1, (ch+1)&1);
        if (more) { CP_WAIT1; } else { CP_WAIT0; }
        __syncthreads();
        const int bq = ch & 1;
        #pragma unroll
        for (int ks = 0; ks < 2; ks++) {
            const int kr = ks*8 + tq;
            #pragma unroll
            for (int t = 0; t < 3; t++) {
                unsigned a[2][4], bf[8][2];
                #pragma unroll
                for (int mt = 0; mt < 2; mt++) {
                    int om = wm*32 + mt*16 + grp;
                    a[mt][0] = Wt[bq][(t*16+kr  )*72 + om];
                    a[mt][1] = Wt[bq][(t*16+kr  )*72 + om+8];
                    a[mt][2] = Wt[bq][(t*16+kr+4)*72 + om];
                    a[mt][3] = Wt[bq][(t*16+kr+4)*72 + om+8];
                }
                #pragma unroll
                for (int nt = 0; nt < 8; nt++) {
                    int cc = wn*64 + nt*8 + grp + t;
                    bf[nt][0] = Xt[bq][kr  ][cc];
                    bf[nt][1] = Xt[bq][kr+4][cc];
                }
                #pragma unroll
                for (int mt = 0; mt < 2; mt++)
                    #pragma unroll
                    for (int nt = 0; nt < 8; nt++)
                        mma_tf32(c[mt][nt], a[mt], bf[nt]);
            }
        }
        __syncthreads();
    }
    if (OOFF > 0) {
        if (blockIdx.y == 0) {
            for (int i = tid; i < 64*OOFF; i += 128)
                out[(size_t)(b*128 + oh*64 + i/OOFF)*OSTR + (i%OOFF)] = 0.f;
        }
        if (p0 + 64 >= JOUT) {
            const int TW = OSTR - OOFF - JOUT;
            for (int i = tid; i < 64*TW; i += 128)
                out[(size_t)(b*128 + oh*64 + i/TW)*OSTR + OOFF + JOUT + (i%TW)] = 0.f;
        }
    }
    #pragma unroll
    for (int mt = 0; mt < 2; mt++) {
        int ocl = wm*32 + mt*16 + grp;
        #pragma unroll
        for (int nt = 0; nt < 8; nt++) {
            int lp = wn*64 + nt*8 + tq*2;
            int j = p0 + (lp >> 1);
            if (j < JOUT) {
                #pragma unroll
                for (int rr = 0; rr < 2; rr++) {
                    int ol = ocl + rr*8;
                    float s = sc[ol], h = sh[ol];
                    float r0 = fmaxf(fmaf(c[mt][nt][rr*2],   s, h), 0.f);
                    float r1 = fmaxf(fmaf(c[mt][nt][rr*2+1], s, h), 0.f);
                    out[(size_t)(b*128 + oh*64 + ol)*OSTR + OOFF + j] = (j == 0) ? r1 : fmaxf(r0, r1);
                }
            }
        }
    }
}

// ---------- map2 GEMM [768,24448]x[24448,256], tf32 MMA, split-K=16 ----------
__global__ __launch_bounds__(128)
void k_map2_mma(const float* __restrict__ A, const float* __restrict__ Bw, float* __restrict__ P) {
    __shared__ unsigned At[2][64][36];
    __shared__ unsigned Bt[2][32][72];
    const int m0 = blockIdx.x*64, n0 = blockIdx.y*64;
    const int k0 = blockIdx.z*1536;
    const int kend = (k0 + 1536 < 24448) ? k0 + 1536 : 24448;
    const int niter = (kend - k0) >> 5;
    const int tid = threadIdx.x, lane = tid & 31, warp = tid >> 5;
    const int wm = warp & 1, wn = warp >> 1;
    const int grp = lane >> 2, tq = lane & 3;
    float c[2][4][4];
    #pragma unroll
    for (int mt = 0; mt < 2; mt++)
        #pragma unroll
        for (int nt = 0; nt < 4; nt++)
            #pragma unroll
            for (int q = 0; q < 4; q++) c[mt][nt][q] = 0.f;

    auto stage = [&](int it, int buf) {
        int kc = k0 + it*32;
        #pragma unroll
        for (int s = 0; s < 4; s++) {
            int idx = tid + 128*s;
            int row = idx >> 3, c4 = idx & 7;
            cpa16(&At[buf][row][c4*4], &A[(size_t)(m0+row)*24448 + kc + c4*4]);
        }
        #pragma unroll
        for (int s = 0; s < 4; s++) {
            int idx = tid + 128*s;
            int row = idx >> 4, c4 = idx & 15;
            cpa16(&Bt[buf][row][c4*4], &Bw[(size_t)(kc+row)*256 + n0 + c4*4]);
        }
        CP_COMMIT;
    };

    stage(0, 0);
    for (int it = 0; it < niter; it++) {
        bool more = (it + 1 < niter);
        if (more) stage(it+1, (it+1)&1);
        if (more) { CP_WAIT1; } else { CP_WAIT0; }
        __syncthreads();
        const int bq = it & 1;
        #pragma unroll
        for (int ks = 0; ks < 4; ks++) {
            const int kr = ks*8 + tq;
            unsigned a[2][4], bf[4][2];
            #pragma unroll
            for (int mt = 0; mt < 2; mt++) {
                int om = wm*32 + mt*16 + grp;
                a[mt][0] = At[bq][om  ][kr];   a[mt][1] = At[bq][om+8][kr];
                a[mt][2] = At[bq][om  ][kr+4]; a[mt][3] = At[bq][om+8][kr+4];
            }
            #pragma unroll
            for (int nt = 0; nt < 4; nt++) {
                int cc = wn*32 + nt*8 + grp;
                bf[nt][0] = Bt[bq][kr  ][cc];
                bf[nt][1] = Bt[bq][kr+4][cc];
            }
            #pragma unroll
            for (int mt = 0; mt < 2; mt++)
                #pragma unroll
                for (int nt = 0; nt < 4; nt++)
                    mma_tf32(c[mt][nt], a[mt], bf[nt]);
        }
        __syncthreads();
    }
    #pragma unroll
    for (int mt = 0; mt < 2; mt++) {
        int row = m0 + wm*32 + mt*16 + grp;
        #pragma unroll
        for (int nt = 0; nt < 4; nt++) {
            int col = n0 + wn*32 + nt*8 + tq*2;
            *(float2*)&P[(size_t)(blockIdx.z*768 + row    )*256 + col] = make_float2(c[mt][nt][0], c[mt][nt][1]);
            *(float2*)&P[(size_t)(blockIdx.z*768 + row + 8)*256 + col] = make_float2(c[mt][nt][2], c[mt][nt][3]);
        }
    }
}

// ---------- split-K combine + bias + BN + positional encoding ----------
__global__ void k_combine(const float* __restrict__ mp, const float* __restrict__ mb,
                          const float* __restrict__ bnm, float* __restrict__ a) {
    const int row = blockIdx.x, f = threadIdx.x;
    float s = 0.f;
    #pragma unroll
    for (int z = 0; z < 16; z++) s += mp[(z*768+row)*256+f];
    s += mb[f];
    s = fmaf(s - bnm[512+f], bnm[f] * rsqrtf(bnm[768+f] + 1e-5f), bnm[256+f]);
    const int t = (row >> 2) % 6;
    const float div = expf((float)((f >> 1) * 2) * (-4.605170185988091f / 256.f));
    const float ang = (float)t * div;
    a[row*256+f] = s + ((f & 1) ? cosf(ang) : sinf(ang));
}

// ---------- fused branch: graphf + adjacency + MPNN for both windows ----------
__global__ __launch_bounds__(256)
void k_branch(const float* __restrict__ a,
              const float* __restrict__ g1_w, const float* __restrict__ g1_b,
              const float* __restrict__ bnA1, const float* __restrict__ th1_w,
              const float* __restrict__ th1_b, const float* __restrict__ bnM1,
              const float* __restrict__ g2_w, const float* __restrict__ g2_b,
              const float* __restrict__ bnA2, const float* __restrict__ th2_w,
              const float* __restrict__ th2_b, const float* __restrict__ bnM2,
              float* __restrict__ feats) {
    const int g = blockIdx.x, tid = threadIdx.x;
    const bool w1 = g < 160;
    const float* gw  = w1 ? g1_w : g2_w;
    const float* gb  = w1 ? g1_b : g2_b;
    const float* bnA = w1 ? bnA1 : bnA2;
    const float* tw  = w1 ? th1_w : th2_w;
    const float* tb  = w1 ? th1_b : th2_b;
    const float* bnM = w1 ? bnM1 : bnM2;
    const int gg = w1 ? g : g - 160;
    const int nw = w1 ? 5 : 3, stride = w1 ? 1 : 2, off = w1 ? 0 : 2560;
    const int bs = gg / nw, j = gg % nw;

    __shared__ float Xc[8][257];
    __shared__ float fs[8][257];
    __shared__ float dots[64];
    __shared__ float Aj[64];
    __shared__ float part[2][8][128];

    #pragma unroll
    for (int n = 0; n < 8; n++) {
        int row = (bs*6 + j*stride + (n>>2))*4 + (n&3);
        Xc[n][tid] = a[row*256 + tid];
    }
    __syncthreads();
    {
        float acc[8], bias = gb[tid];
        #pragma unroll
        for (int n = 0; n < 8; n++) acc[n] = bias;
        #pragma unroll 4
        for (int d = 0; d < 256; d++) {
            float wv = gw[d*256 + tid];
            #pragma unroll
            for (int n = 0; n < 8; n++) acc[n] = fmaf(Xc[n][d], wv, acc[n]);
        }
        #pragma unroll
        for (int n = 0; n < 8; n++) fs[n][tid] = acc[n];
    }
    __syncthreads();
    {
        int pr = tid >> 2, tq = tid & 3, n = pr >> 3, m = pr & 7;
        float dp = 0.f;
        #pragma unroll 4
        for (int i = 0; i < 64; i++) {
            int d = tq*64 + i;
            dp = fmaf(fs[n][d], fs[m][d], dp);
        }
        dp += __shfl_xor_sync(0xffffffffu, dp, 1, 4);
        dp += __shfl_xor_sync(0xffffffffu, dp, 2, 4);
        if (tq == 0) dots[pr] = dp;
    }
    __syncthreads();
    if (tid < 64) {
        int n = tid >> 3, m = tid & 7;
        float dot = dots[tid];
        if (n == m) dot -= 1e8f;
        float v = dot > 0.f ? dot : 0.01f*dot;
        float mx = v;
        #pragma unroll
        for (int o = 1; o < 8; o <<= 1) mx = fmaxf(mx, __shfl_xor_sync(0xffffffffu, mx, o, 8));
        float e = expf(v - mx), ssum = e;
        #pragma unroll
        for (int o = 1; o < 8; o <<= 1) ssum += __shfl_xor_sync(0xffffffffu, ssum, o, 8);
        float av = e / ssum;
        if (n == m) av += 1.f;
        Aj[tid] = av * (((n>>2) == (m>>2)) ? 1.f : 0.7f);
    }
    {
        float s = bnA[tid] * rsqrtf(bnA[768+tid] + 1e-5f);
        float sh = bnA[256+tid] - bnA[512+tid]*s;
        #pragma unroll
        for (int n = 0; n < 8; n++) Xc[n][tid] = fmaf(Xc[n][tid], s, sh);
    }
    __syncthreads();
    #pragma unroll
    for (int n = 0; n < 8; n++) {
        float ys = 0.f;
        #pragma unroll
        for (int m = 0; m < 8; m++) ys = fmaf(Aj[n*8+m], Xc[m][tid], ys);
        fs[n][tid] = ys;
    }
    __syncthreads();
    {
        int half = tid >> 7, o = tid & 127;
        float hac[8];
        #pragma unroll
        for (int n = 0; n < 8; n++) hac[n] = 0.f;
        #pragma unroll 4
        for (int dd = 0; dd < 128; dd++) {
            int d = half*128 + dd;
            float wv = tw[d*128 + o];
            #pragma unroll
            for (int n = 0; n < 8; n++) hac[n] = fmaf(fs[n][d], wv, hac[n]);
        }
        #pragma unroll
        for (int n = 0; n < 8; n++) part[half][n][o] = hac[n];
    }
    __syncthreads();
    if (tid < 128) {
        int o = tid;
        float s = bnM[o] * rsqrtf(bnM[384+o] + 1e-5f);
        float sh = bnM[128+o] - bnM[256+o]*s;
        float hv[8];
        #pragma unroll
        for (int n = 0; n < 8; n++) {
            float z = part[0][n][o] + part[1][n][o] + tb[o];
            z = fmaf(z, s, sh);
            hv[n] = z > 0.f ? z : 0.01f*z;
        }
        #pragma unroll
        for (int ns = 0; ns < 4; ns++)
            feats[bs*4096 + off + (j*4+ns)*128 + o] = 0.5f*(hv[ns] + hv[4+ns]);
    }
}

// ---------- fc1 split-K partials ----------
__global__ __launch_bounds__(256)
void k_fc1p(const float* __restrict__ x, const float* __restrict__ w, float* __restrict__ P) {
    __shared__ float xs[1024];
    const int row = blockIdx.x, ks = blockIdx.y, tid = threadIdx.x;
    for (int i = tid; i < 1024; i += 256) xs[i] = x[row*4096 + ks*1024 + i];
    __syncthreads();
    float a0 = 0.f, a1 = 0.f, a2 = 0.f, a3 = 0.f;
    const float* wp = w + (size_t)ks*1024*256 + tid;
    for (int k = 0; k < 1024; k += 4) {
        a0 = fmaf(xs[k],   wp[(size_t)k*256],       a0);
        a1 = fmaf(xs[k+1], wp[(size_t)(k+1)*256],   a1);
        a2 = fmaf(xs[k+2], wp[(size_t)(k+2)*256],   a2);
        a3 = fmaf(xs[k+3], wp[(size_t)(k+3)*256],   a3);
    }
    P[(ks*32 + row)*256 + tid] = (a0 + a1) + (a2 + a3);
}

// ---------- fc1-combine + relu + fc2 + fc3 + fc4 fused ----------
__global__ __launch_bounds__(256)
void k_fchain(const float* __restrict__ P, const float* __restrict__ b1,
              const float* __restrict__ w2, const float* __restrict__ b2,
              const float* __restrict__ w3, const float* __restrict__ b3,
              const float* __restrict__ w4, const float* __restrict__ b4,
              float* __restrict__ out) {
    __shared__ float xs[256], ys[256], zs[128];
    const int row = blockIdx.x, tid = threadIdx.x;
    {
        float v = P[row*256+tid] + P[(32+row)*256+tid] + P[(64+row)*256+tid] + P[(96+row)*256+tid];
        xs[tid] = fmaxf(v + b1[tid], 0.f);
    }
    __syncthreads();
    {
        float acc = b2[tid];
        #pragma unroll 4
        for (int k = 0; k < 256; k++) acc = fmaf(xs[k], w2[k*256+tid], acc);
        ys[tid] = fmaxf(acc, 0.f);
    }
    __syncthreads();
    if (tid < 128) {
        float acc = b3[tid];
        #pragma unroll 4
        for (int k = 0; k < 256; k++) acc = fmaf(ys[k], w3[k*128+tid], acc);
        zs[tid] = fmaxf(acc, 0.f);
    }
    __syncthreads();
    if (tid < 5) {
        float acc = b4[tid];
        for (int k = 0; k < 128; k++) acc = fmaf(zs[k], w4[k*5+tid], acc);
        out[row*5+tid] = acc;
    }
}

extern "C" void kernel_launch(void* const* d_in, const int* in_sizes, int n_in,
                              void* d_out, int out_size) {
    const float* X       = (const float*)d_in[0];
    const float* conv1_w = (const float*)d_in[1];
    const float* bn1     = (const float*)d_in[2];
    const float* conv2_w = (const float*)d_in[3];
    const float* bn2     = (const float*)d_in[4];
    const float* conv3_w = (const float*)d_in[5];
    const float* bn3     = (const float*)d_in[6];
    const float* map2_w  = (const float*)d_in[7];
    const float* map2_b  = (const float*)d_in[8];
    const float* bn_map2 = (const float*)d_in[9];
    const float* g1_w = (const float*)d_in[10], *g1_b = (const float*)d_in[11], *bnA1 = (const float*)d_in[12];
    const float* th1_w = (const float*)d_in[13], *th1_b = (const float*)d_in[14], *bnM1 = (const float*)d_in[15];
    const float* g2_w = (const float*)d_in[16], *g2_b = (const float*)d_in[17], *bnA2 = (const float*)d_in[18];
    const float* th2_w = (const float*)d_in[19], *th2_b = (const float*)d_in[20], *bnM2 = (const float*)d_in[21];
    const float* fc1_w = (const float*)d_in[22], *fc1_b = (const float*)d_in[23];
    const float* fc2_w = (const float*)d_in[24], *fc2_b = (const float*)d_in[25];
    const float* fc3_w = (const float*)d_in[26], *fc3_b = (const float*)d_in[27];
    const float* fc4_w = (const float*)d_in[28], *fc4_b = (const float*)d_in[29];

    void* p;
    cudaGetSymbolAddress(&p, g_s1);   float* s1 = (float*)p;
    cudaGetSymbolAddress(&p, g_s2);   float* s2 = (float*)p;
    cudaGetSymbolAddress(&p, g_s3);   float* s3 = (float*)p;
    cudaGetSymbolAddress(&p, g_wt2);  float* wt2 = (float*)p;
    cudaGetSymbolAddress(&p, g_wt3);  float* wt3 = (float*)p;
    cudaGetSymbolAddress(&p, g_mp);   float* mp = (float*)p;
    cudaGetSymbolAddress(&p, g_a);    float* a  = (float*)p;
    cudaGetSymbolAddress(&p, g_feats);float* feats = (float*)p;

    k_wt<<<(128*64*3+255)/256, 256>>>(conv2_w, wt2, 64);
    k_wt<<<(128*128*3+255)/256, 256>>>(conv3_w, wt3, 128);
    k_conv1<<<dim3(768,3), 256>>>(X, conv1_w, bn1, s1);
    k_conv_mma<64,2,S1R,7,377,S2R,8><<<dim3(768,6,2), 128>>>(s1, wt2, bn2, s2);
    k_conv_mma<128,3,S2R,8,191,191,0><<<dim3(768,3,2), 128>>>(s2, wt3, bn3, s3);
    k_map2_mma<<<dim3(12,4,16), 128>>>(s3, map2_w, mp);
    k_combine<<<768, 256>>>(mp, map2_b, bn_map2, a);
    k_branch<<<256, 256>>>(a, g1_w, g1_b, bnA1, th1_w, th1_b, bnM1,
                              g2_w, g2_b, bnA2, th2_w, th2_b, bnM2, feats);
    k_fc1p<<<dim3(32,4), 256>>>(feats, fc1_w, mp);
    k_fchain<<<32, 256>>>(mp, fc1_b, fc2_w, fc2_b, fc3_w, fc3_b, fc4_w, fc4_b, (float*)d_out);
}

// round 17
// speedup vs baseline: 1.0224x; 1.0217x over previous
#include <cuda_runtime.h>
#include <math.h>

// ---------- tf32 MMA (raw fp32 bits; HW truncates to tf32) ----------
__device__ __forceinline__ void mma_tf32(float* d, const unsigned* a, const unsigned* b) {
    asm("mma.sync.aligned.m16n8k8.row.col.f32.tf32.tf32.f32 "
        "{%0,%1,%2,%3}, {%4,%5,%6,%7}, {%8,%9}, {%0,%1,%2,%3};"
        : "+f"(d[0]), "+f"(d[1]), "+f"(d[2]), "+f"(d[3])
        : "r"(a[0]), "r"(a[1]), "r"(a[2]), "r"(a[3]), "r"(b[0]), "r"(b[1]));
}
__device__ __forceinline__ void cpa16(void* dst, const void* src) {
    unsigned s = (unsigned)__cvta_generic_to_shared(dst);
    asm volatile("cp.async.cg.shared.global [%0], [%1], 16;" :: "r"(s), "l"(src));
}
#define CP_COMMIT asm volatile("cp.async.commit_group;")
#define CP_WAIT1  asm volatile("cp.async.wait_group 1;")
#define CP_WAIT0  asm volatile("cp.async.wait_group 0;")

#define S1R 780   // s1 row stride; data at [7, 7+751)
#define S2R 396   // s2 row stride; data at [8, 8+377)

// ---------- scratch ----------
__device__ float g_s1[768*64*S1R];
__device__ float g_s2[768*128*S2R];
__device__ float g_s3[768*128*191];
__device__ float g_wt2[64*3*128];
__device__ float g_wt3[128*3*128];
__device__ float g_mp[16*768*256];
__device__ float g_a [768*256];
__device__ float g_feats[32*4096];

// ---------- weight transpose: w[oc][ic][tap] -> wT[ch][tap*16+icl][oc] ----------
__global__ void k_wt(const float* __restrict__ w, float* __restrict__ wT, int IC) {
    int idx = blockIdx.x*256 + threadIdx.x;
    if (idx >= 128*IC*3) return;
    int oc = idx / (IC*3), r = idx - oc*(IC*3);
    int ic = r / 3, tap = r - ic*3;
    int ch = ic >> 4, icl = ic & 15;
    wT[ch*6144 + (tap*16+icl)*128 + oc] = w[idx];
}

// ---------- conv1 (1->64,K=3,pad=1)+BN+ReLU+maxpool2(pad=1): coalesced, 1 pooled/thread ----------
__global__ __launch_bounds__(256)
void k_conv1(const float* __restrict__ x, const float* __restrict__ w,
             const float* __restrict__ bn, float* __restrict__ out) {
    __shared__ float xs[516];
    __shared__ float ws[192];
    __shared__ float sc[64], sh[64];
    const int b = blockIdx.x, j0 = blockIdx.y * 256, tid = threadIdx.x;
    if (tid < 192) ws[tid] = w[tid];
    if (tid >= 192 && tid < 256) {
        int o = tid - 192;
        float s = bn[o] * rsqrtf(bn[192+o] + 1e-5f);
        sc[o] = s; sh[o] = bn[64+o] - bn[128+o]*s;
    }
    const int base = 2*j0 - 2;
    for (int i = tid; i < 514; i += 256) {
        int gi = base + i;
        xs[i] = (gi >= 0 && gi < 1500) ? x[b*1500 + gi] : 0.f;
    }
    __syncthreads();
    if (blockIdx.y == 0) {
        for (int i = tid; i < 64*7; i += 256)
            out[(size_t)(b*64 + i/7)*S1R + (i%7)] = 0.f;
    } else if (blockIdx.y == 2) {
        for (int i = tid; i < 64*22; i += 256)
            out[(size_t)(b*64 + i/22)*S1R + 758 + (i%22)] = 0.f;
    }
    const int j = j0 + tid;
    if (j > 750) return;
    const float a0 = xs[2*tid], a1 = xs[2*tid+1], a2 = xs[2*tid+2], a3 = xs[2*tid+3];
    const bool vL = (j > 0), vR = (j < 750);
    float* ob = out + (size_t)b*64*S1R + 7 + j;
    #pragma unroll 4
    for (int oc = 0; oc < 64; oc++) {
        float w0 = ws[3*oc], w1 = ws[3*oc+1], w2 = ws[3*oc+2];
        float s = sc[oc], h = sh[oc];
        float r0 = fmaf(w2, a2, fmaf(w1, a1, w0*a0));
        float r1 = fmaf(w2, a3, fmaf(w1, a2, w0*a1));
        r0 = fmaxf(fmaf(r0, s, h), 0.f);
        r1 = fmaxf(fmaf(r1, s, h), 0.f);
        ob[(size_t)oc*S1R] = fmaxf(vL ? r0 : -1e30f, vR ? r1 : -1e30f);
    }
}

// ---------- conv (IC->128,K=3)+BN+ReLU+pool via tf32 MMA, 3-stage ring / 1 barrier ----------
// 128 thr = 4 warps (2wm x 2wn); warp tile 64oc x 64 conv pos; block 128 x 128 (64 pooled).
template<int IC, int PAD, int XSTR, int XOFF, int JOUT, int OSTR, int OOFF>
__global__ __launch_bounds__(128, 2)
void k_conv_mma(const float* __restrict__ x, const float* __restrict__ wT,
                const float* __restrict__ bn, float* __restrict__ out) {
    __shared__ unsigned Wt[3][48*136];
    __shared__ unsigned Xt[3][16][136];
    __shared__ float sc[128], sh[128];
    const int b = blockIdx.x, p0 = blockIdx.y * 64;
    const int tid = threadIdx.x, lane = tid & 31, warp = tid >> 5;
    const int wm = warp & 1, wn = warp >> 1;
    const int grp = lane >> 2, tq = lane & 3;
    {
        float s = bn[tid] * rsqrtf(bn[384+tid] + 1e-5f);
        sc[tid] = s; sh[tid] = bn[128+tid] - bn[256+tid]*s;
    }
    float c[4][8][4];
    #pragma unroll
    for (int mt = 0; mt < 4; mt++)
        #pragma unroll
        for (int nt = 0; nt < 8; nt++)
            #pragma unroll
            for (int q = 0; q < 4; q++) c[mt][nt][q] = 0.f;
    const int xbase = XOFF + 2*p0 - 1 - PAD;
    const float* xb = x + (size_t)b*IC*XSTR;
    const int NCH = IC/16;

    auto stage = [&](int ch, int buf) {
        for (int i = tid; i < 1536; i += 128) {
            int row = i >> 5, col4 = i & 31;
            cpa16(&Wt[buf][row*136 + col4*4], wT + (size_t)ch*6144 + row*128 + col4*4);
        }
        for (int i = tid; i < 16*34; i += 128) {
            int r = i / 34, c4 = i - r*34;
            cpa16(&Xt[buf][r][c4*4], xb + (size_t)(ch*16+r)*XSTR + xbase + c4*4);
        }
        CP_COMMIT;
    };

    stage(0, 0);
    if (NCH > 1) stage(1, 1);
    int bq = 0;
    for (int ch = 0; ch < NCH; ch++) {
        if (ch + 1 < NCH) { CP_WAIT1; } else { CP_WAIT0; }
        __syncthreads();                 // single barrier per chunk
        if (ch + 2 < NCH) {
            int nb = bq + 2; if (nb >= 3) nb -= 3;
            stage(ch + 2, nb);           // writes buffer last read at ch-1 (idle)
        }
        #pragma unroll
        for (int ks = 0; ks < 2; ks++) {
            const int kr = ks*8 + tq;
            #pragma unroll
            for (int t = 0; t < 3; t++) {
                unsigned a[4][4], bf[8][2];
                #pragma unroll
                for (int mt = 0; mt < 4; mt++) {
                    int om = wm*64 + mt*16 + grp;
                    a[mt][0] = Wt[bq][(t*16+kr  )*136 + om];
                    a[mt][1] = Wt[bq][(t*16+kr  )*136 + om+8];
                    a[mt][2] = Wt[bq][(t*16+kr+4)*136 + om];
                    a[mt][3] = Wt[bq][(t*16+kr+4)*136 + om+8];
                }
                #pragma unroll
                for (int nt = 0; nt < 8; nt++) {
                    int cc = wn*64 + nt*8 + grp + t;
                    bf[nt][0] = Xt[bq][kr  ][cc];
                    bf[nt][1] = Xt[bq][kr+4][cc];
                }
                #pragma unroll
                for (int mt = 0; mt < 4; mt++)
                    #pragma unroll
                    for (int nt = 0; nt < 8; nt++)
                        mma_tf32(c[mt][nt], a[mt], bf[nt]);
            }
        }
        if (++bq >= 3) bq = 0;
    }
    if (OOFF > 0) {
        if (blockIdx.y == 0) {
            for (int i = tid; i < 128*OOFF; i += 128)
                out[(size_t)(b*128 + i/OOFF)*OSTR + (i%OOFF)] = 0.f;
        }
        if (p0 + 64 >= JOUT) {
            const int TW = OSTR - OOFF - JOUT;
            for (int i = tid; i < 128*TW; i += 128)
                out[(size_t)(b*128 + i/TW)*OSTR + OOFF + JOUT + (i%TW)] = 0.f;
        }
    }
    #pragma unroll
    for (int mt = 0; mt < 4; mt++) {
        int ocr = wm*64 + mt*16 + grp;
        #pragma unroll
        for (int nt = 0; nt < 8; nt++) {
            int lp = wn*64 + nt*8 + tq*2;
            int j = p0 + (lp >> 1);
            if (j < JOUT) {
                #pragma unroll
                for (int rr = 0; rr < 2; rr++) {
                    int oc = ocr + rr*8;
                    float s = sc[oc], h = sh[oc];
                    float r0 = fmaxf(fmaf(c[mt][nt][rr*2],   s, h), 0.f);
                    float r1 = fmaxf(fmaf(c[mt][nt][rr*2+1], s, h), 0.f);
                    out[(size_t)(b*128+oc)*OSTR + OOFF + j] = (j == 0) ? r1 : fmaxf(r0, r1);
                }
            }
        }
    }
}

// ---------- map2 GEMM [768,24448]x[24448,256], tf32 MMA, split-K=16 ----------
__global__ __launch_bounds__(128)
void k_map2_mma(const float* __restrict__ A, const float* __restrict__ Bw, float* __restrict__ P) {
    __shared__ unsigned At[2][64][36];
    __shared__ unsigned Bt[2][32][72];
    const int m0 = blockIdx.x*64, n0 = blockIdx.y*64;
    const int k0 = blockIdx.z*1536;
    const int kend = (k0 + 1536 < 24448) ? k0 + 1536 : 24448;
    const int niter = (kend - k0) >> 5;
    const int tid = threadIdx.x, lane = tid & 31, warp = tid >> 5;
    const int wm = warp & 1, wn = warp >> 1;
    const int grp = lane >> 2, tq = lane & 3;
    float c[2][4][4];
    #pragma unroll
    for (int mt = 0; mt < 2; mt++)
        #pragma unroll
        for (int nt = 0; nt < 4; nt++)
            #pragma unroll
            for (int q = 0; q < 4; q++) c[mt][nt][q] = 0.f;

    auto stage = [&](int it, int buf) {
        int kc = k0 + it*32;
        #pragma unroll
        for (int s = 0; s < 4; s++) {
            int idx = tid + 128*s;
            int row = idx >> 3, c4 = idx & 7;
            cpa16(&At[buf][row][c4*4], &A[(size_t)(m0+row)*24448 + kc + c4*4]);
        }
        #pragma unroll
        for (int s = 0; s < 4; s++) {
            int idx = tid + 128*s;
            int row = idx >> 4, c4 = idx & 15;
            cpa16(&Bt[buf][row][c4*4], &Bw[(size_t)(kc+row)*256 + n0 + c4*4]);
        }
        CP_COMMIT;
    };

    stage(0, 0);
    for (int it = 0; it < niter; it++) {
        bool more = (it + 1 < niter);
        if (more) stage(it+1, (it+1)&1);
        if (more) { CP_WAIT1; } else { CP_WAIT0; }
        __syncthreads();
        const int bq = it & 1;
        #pragma unroll
        for (int ks = 0; ks < 4; ks++) {
            const int kr = ks*8 + tq;
            unsigned a[2][4], bf[4][2];
            #pragma unroll
            for (int mt = 0; mt < 2; mt++) {
                int om = wm*32 + mt*16 + grp;
                a[mt][0] = At[bq][om  ][kr];   a[mt][1] = At[bq][om+8][kr];
                a[mt][2] = At[bq][om  ][kr+4]; a[mt][3] = At[bq][om+8][kr+4];
            }
            #pragma unroll
            for (int nt = 0; nt < 4; nt++) {
                int cc = wn*32 + nt*8 + grp;
                bf[nt][0] = Bt[bq][kr  ][cc];
                bf[nt][1] = Bt[bq][kr+4][cc];
            }
            #pragma unroll
            for (int mt = 0; mt < 2; mt++)
                #pragma unroll
                for (int nt = 0; nt < 4; nt++)
                    mma_tf32(c[mt][nt], a[mt], bf[nt]);
        }
        __syncthreads();
    }
    #pragma unroll
    for (int mt = 0; mt < 2; mt++) {
        int row = m0 + wm*32 + mt*16 + grp;
        #pragma unroll
        for (int nt = 0; nt < 4; nt++) {
            int col = n0 + wn*32 + nt*8 + tq*2;
            *(float2*)&P[(size_t)(blockIdx.z*768 + row    )*256 + col] = make_float2(c[mt][nt][0], c[mt][nt][1]);
            *(float2*)&P[(size_t)(blockIdx.z*768 + row + 8)*256 + col] = make_float2(c[mt][nt][2], c[mt][nt][3]);
        }
    }
}

// ---------- split-K combine + bias + BN + positional encoding ----------
__global__ void k_combine(const float* __restrict__ mp, const float* __restrict__ mb,
                          const float* __restrict__ bnm, float* __restrict__ a) {
    const int row = blockIdx.x, f = threadIdx.x;
    float s = 0.f;
    #pragma unroll
    for (int z = 0; z < 16; z++) s += mp[(z*768+row)*256+f];
    s += mb[f];
    s = fmaf(s - bnm[512+f], bnm[f] * rsqrtf(bnm[768+f] + 1e-5f), bnm[256+f]);
    const int t = (row >> 2) % 6;
    const float div = expf((float)((f >> 1) * 2) * (-4.605170185988091f / 256.f));
    const float ang = (float)t * div;
    a[row*256+f] = s + ((f & 1) ? cosf(ang) : sinf(ang));
}

// ---------- fused branch: graphf + adjacency + MPNN for both windows ----------
__global__ __launch_bounds__(256)
void k_branch(const float* __restrict__ a,
              const float* __restrict__ g1_w, const float* __restrict__ g1_b,
              const float* __restrict__ bnA1, const float* __restrict__ th1_w,
              const float* __restrict__ th1_b, const float* __restrict__ bnM1,
              const float* __restrict__ g2_w, const float* __restrict__ g2_b,
              const float* __restrict__ bnA2, const float* __restrict__ th2_w,
              const float* __restrict__ th2_b, const float* __restrict__ bnM2,
              float* __restrict__ feats) {
    const int g = blockIdx.x, tid = threadIdx.x;
    const bool w1 = g < 160;
    const float* gw  = w1 ? g1_w : g2_w;
    const float* gb  = w1 ? g1_b : g2_b;
    const float* bnA = w1 ? bnA1 : bnA2;
    const float* tw  = w1 ? th1_w : th2_w;
    const float* tb  = w1 ? th1_b : th2_b;
    const float* bnM = w1 ? bnM1 : bnM2;
    const int gg = w1 ? g : g - 160;
    const int nw = w1 ? 5 : 3, stride = w1 ? 1 : 2, off = w1 ? 0 : 2560;
    const int bs = gg / nw, j = gg % nw;

    __shared__ float Xc[8][257];
    __shared__ float fs[8][257];
    __shared__ float dots[64];
    __shared__ float Aj[64];
    __shared__ float part[2][8][128];

    #pragma unroll
    for (int n = 0; n < 8; n++) {
        int row = (bs*6 + j*stride + (n>>2))*4 + (n&3);
        Xc[n][tid] = a[row*256 + tid];
    }
    __syncthreads();
    {
        float acc[8], bias = gb[tid];
        #pragma unroll
        for (int n = 0; n < 8; n++) acc[n] = bias;
        #pragma unroll 4
        for (int d = 0; d < 256; d++) {
            float wv = gw[d*256 + tid];
            #pragma unroll
            for (int n = 0; n < 8; n++) acc[n] = fmaf(Xc[n][d], wv, acc[n]);
        }
        #pragma unroll
        for (int n = 0; n < 8; n++) fs[n][tid] = acc[n];
    }
    __syncthreads();
    {
        int pr = tid >> 2, tq = tid & 3, n = pr >> 3, m = pr & 7;
        float dp = 0.f;
        #pragma unroll 4
        for (int i = 0; i < 64; i++) {
            int d = tq*64 + i;
            dp = fmaf(fs[n][d], fs[m][d], dp);
        }
        dp += __shfl_xor_sync(0xffffffffu, dp, 1, 4);
        dp += __shfl_xor_sync(0xffffffffu, dp, 2, 4);
        if (tq == 0) dots[pr] = dp;
    }
    __syncthreads();
    if (tid < 64) {
        int n = tid >> 3, m = tid & 7;
        float dot = dots[tid];
        if (n == m) dot -= 1e8f;
        float v = dot > 0.f ? dot : 0.01f*dot;
        float mx = v;
        #pragma unroll
        for (int o = 1; o < 8; o <<= 1) mx = fmaxf(mx, __shfl_xor_sync(0xffffffffu, mx, o, 8));
        float e = expf(v - mx), ssum = e;
        #pragma unroll
        for (int o = 1; o < 8; o <<= 1) ssum += __shfl_xor_sync(0xffffffffu, ssum, o, 8);
        float av = e / ssum;
        if (n == m) av += 1.f;
        Aj[tid] = av * (((n>>2) == (m>>2)) ? 1.f : 0.7f);
    }
    {
        float s = bnA[tid] * rsqrtf(bnA[768+tid] + 1e-5f);
        float sh = bnA[256+tid] - bnA[512+tid]*s;
        #pragma unroll
        for (int n = 0; n < 8; n++) Xc[n][tid] = fmaf(Xc[n][tid], s, sh);
    }
    __syncthreads();
    #pragma unroll
    for (int n = 0; n < 8; n++) {
        float ys = 0.f;
        #pragma unroll
        for (int m = 0; m < 8; m++) ys = fmaf(Aj[n*8+m], Xc[m][tid], ys);
        fs[n][tid] = ys;
    }
    __syncthreads();
    {
        int half = tid >> 7, o = tid & 127;
        float hac[8];
        #pragma unroll
        for (int n = 0; n < 8; n++) hac[n] = 0.f;
        #pragma unroll 4
        for (int dd = 0; dd < 128; dd++) {
            int d = half*128 + dd;
            float wv = tw[d*128 + o];
            #pragma unroll
            for (int n = 0; n < 8; n++) hac[n] = fmaf(fs[n][d], wv, hac[n]);
        }
        #pragma unroll
        for (int n = 0; n < 8; n++) part[half][n][o] = hac[n];
    }
    __syncthreads();
    if (tid < 128) {
        int o = tid;
        float s = bnM[o] * rsqrtf(bnM[384+o] + 1e-5f);
        float sh = bnM[128+o] - bnM[256+o]*s;
        float hv[8];
        #pragma unroll
        for (int n = 0; n < 8; n++) {
            float z = part[0][n][o] + part[1][n][o] + tb[o];
            z = fmaf(z, s, sh);
            hv[n] = z > 0.f ? z : 0.01f*z;
        }
        #pragma unroll
        for (int ns = 0; ns < 4; ns++)
            feats[bs*4096 + off + (j*4+ns)*128 + o] = 0.5f*(hv[ns] + hv[4+ns]);
    }
}

// ---------- fc1 split-K partials ----------
__global__ __launch_bounds__(256)
void k_fc1p(const float* __restrict__ x, const float* __restrict__ w, float* __restrict__ P) {
    __shared__ float xs[1024];
    const int row = blockIdx.x, ks = blockIdx.y, tid = threadIdx.x;
    for (int i = tid; i < 1024; i += 256) xs[i] = x[row*4096 + ks*1024 + i];
    __syncthreads();
    float a0 = 0.f, a1 = 0.f, a2 = 0.f, a3 = 0.f;
    const float* wp = w + (size_t)ks*1024*256 + tid;
    for (int k = 0; k < 1024; k += 4) {
        a0 = fmaf(xs[k],   wp[(size_t)k*256],       a0);
        a1 = fmaf(xs[k+1], wp[(size_t)(k+1)*256],   a1);
        a2 = fmaf(xs[k+2], wp[(size_t)(k+2)*256],   a2);
        a3 = fmaf(xs[k+3], wp[(size_t)(k+3)*256],   a3);
    }
    P[(ks*32 + row)*256 + tid] = (a0 + a1) + (a2 + a3);
}

// ---------- fc1-combine + relu + fc2 + fc3 + fc4 fused ----------
__global__ __launch_bounds__(256)
void k_fchain(const float* __restrict__ P, const float* __restrict__ b1,
              const float* __restrict__ w2, const float* __restrict__ b2,
              const float* __restrict__ w3, const float* __restrict__ b3,
              const float* __restrict__ w4, const float* __restrict__ b4,
              float* __restrict__ out) {
    __shared__ float xs[256], ys[256], zs[128];
    const int row = blockIdx.x, tid = threadIdx.x;
    {
        float v = P[row*256+tid] + P[(32+row)*256+tid] + P[(64+row)*256+tid] + P[(96+row)*256+tid];
        xs[tid] = fmaxf(v + b1[tid], 0.f);
    }
    __syncthreads();
    {
        float acc = b2[tid];
        #pragma unroll 4
        for (int k = 0; k < 256; k++) acc = fmaf(xs[k], w2[k*256+tid], acc);
        ys[tid] = fmaxf(acc, 0.f);
    }
    __syncthreads();
    if (tid < 128) {
        float acc = b3[tid];
        #pragma unroll 4
        for (int k = 0; k < 256; k++) acc = fmaf(ys[k], w3[k*128+tid], acc);
        zs[tid] = fmaxf(acc, 0.f);
    }
    __syncthreads();
    if (tid < 5) {
        float acc = b4[tid];
        for (int k = 0; k < 128; k++) acc = fmaf(zs[k], w4[k*5+tid], acc);
        out[row*5+tid] = acc;
    }
}

extern "C" void kernel_launch(void* const* d_in, const int* in_sizes, int n_in,
                              void* d_out, int out_size) {
    const float* X       = (const float*)d_in[0];
    const float* conv1_w = (const float*)d_in[1];
    const float* bn1     = (const float*)d_in[2];
    const float* conv2_w = (const float*)d_in[3];
    const float* bn2     = (const float*)d_in[4];
    const float* conv3_w = (const float*)d_in[5];
    const float* bn3     = (const float*)d_in[6];
    const float* map2_w  = (const float*)d_in[7];
    const float* map2_b  = (const float*)d_in[8];
    const float* bn_map2 = (const float*)d_in[9];
    const float* g1_w = (const float*)d_in[10], *g1_b = (const float*)d_in[11], *bnA1 = (const float*)d_in[12];
    const float* th1_w = (const float*)d_in[13], *th1_b = (const float*)d_in[14], *bnM1 = (const float*)d_in[15];
    const float* g2_w = (const float*)d_in[16], *g2_b = (const float*)d_in[17], *bnA2 = (const float*)d_in[18];
    const float* th2_w = (const float*)d_in[19], *th2_b = (const float*)d_in[20], *bnM2 = (const float*)d_in[21];
    const float* fc1_w = (const float*)d_in[22], *fc1_b = (const float*)d_in[23];
    const float* fc2_w = (const float*)d_in[24], *fc2_b = (const float*)d_in[25];
    const float* fc3_w = (const float*)d_in[26], *fc3_b = (const float*)d_in[27];
    const float* fc4_w = (const float*)d_in[28], *fc4_b = (const float*)d_in[29];

    void* p;
    cudaGetSymbolAddress(&p, g_s1);   float* s1 = (float*)p;
    cudaGetSymbolAddress(&p, g_s2);   float* s2 = (float*)p;
    cudaGetSymbolAddress(&p, g_s3);   float* s3 = (float*)p;
    cudaGetSymbolAddress(&p, g_wt2);  float* wt2 = (float*)p;
    cudaGetSymbolAddress(&p, g_wt3);  float* wt3 = (float*)p;
    cudaGetSymbolAddress(&p, g_mp);   float* mp = (float*)p;
    cudaGetSymbolAddress(&p, g_a);    float* a  = (float*)p;
    cudaGetSymbolAddress(&p, g_feats);float* feats = (float*)p;

    k_wt<<<(128*64*3+255)/256, 256>>>(conv2_w, wt2, 64);
    k_wt<<<(128*128*3+255)/256, 256>>>(conv3_w, wt3, 128);
    k_conv1<<<dim3(768,3), 256>>>(X, conv1_w, bn1, s1);
    k_conv_mma<64,2,S1R,7,377,S2R,8><<<dim3(768,6), 128>>>(s1, wt2, bn2, s2);
    k_conv_mma<128,3,S2R,8,191,191,0><<<dim3(768,3), 128>>>(s2, wt3, bn3, s3);
    k_map2_mma<<<dim3(12,4,16), 128>>>(s3, map2_w, mp);
    k_combine<<<768, 256>>>(mp, map2_b, bn_map2, a);
    k_branch<<<256, 256>>>(a, g1_w, g1_b, bnA1, th1_w, th1_b, bnM1,
                              g2_w, g2_b, bnA2, th2_w, th2_b, bnM2, feats);
    k_fc1p<<<dim3(32,4), 256>>>(feats, fc1_w, mp);
    k_fchain<<<32, 256>>>(mp, fc1_b, fc2_w, fc2_b, fc3_w, fc3_b, fc4_w, fc4_b, (float*)d_out);
}